// round 3
// baseline (speedup 1.0000x reference)
#include <cuda_runtime.h>
#include <cuda_fp16.h>

// Problem constants (from reference): N=50000, D=128, E=625000
#define N_NODE   50000
#define D_FEAT   128
#define N_EDGE_MAX 625000
#define SIM_THRESH 0.1f
#define BAND 2.0e-3f   // fp16 sim error is ~1e-4 RMS; 2e-3 band is >10 sigma

// Scratch (device globals — no allocation allowed in kernel_launch)
__device__ float g_inv_nrm[N_NODE];           // 1 / max(||f||, 1e-12)
__device__ float g_row_sum[N_NODE];           // L1 row sums of thresholded sim
__device__ float g_sim[N_EDGE_MAX];           // thresholded per-edge sim (exact fp32)
__device__ int   g_idx_stride;                // 1 = int32 edge_index, 2 = int64
__device__ __align__(16) __half g_fn[(size_t)N_NODE * D_FEAT];  // normalized fp16 feats

// ---------------------------------------------------------------------------
// Kernel 1: per-node inverse norm (warp per node), write normalized fp16
// features, zero row_sum, and detect edge_index dtype (thread 0).
// ---------------------------------------------------------------------------
__global__ void norm_kernel(const float* __restrict__ feat,
                            const int* __restrict__ ei,
                            int n_node) {
    int tid  = blockIdx.x * blockDim.x + threadIdx.x;
    int warp = tid >> 5;
    int lane = threadIdx.x & 31;

    if (tid == 0) {
        // int64 little-endian => odd 32-bit words of first 8 indices all zero
        bool all_hi_zero = true;
        #pragma unroll
        for (int i = 0; i < 8; i++)
            if (ei[2 * i + 1] != 0) all_hi_zero = false;
        g_idx_stride = all_hi_zero ? 2 : 1;
    }
    if (tid < n_node) g_row_sum[tid] = 0.0f;
    if (warp >= n_node) return;

    const float4* fr = reinterpret_cast<const float4*>(feat + (size_t)warp * D_FEAT);
    float4 a = fr[lane];                       // 32 lanes * 4 floats = 128
    float s = a.x * a.x + a.y * a.y + a.z * a.z + a.w * a.w;
    #pragma unroll
    for (int off = 16; off > 0; off >>= 1)
        s += __shfl_xor_sync(0xFFFFFFFFu, s, off);   // all lanes get the sum

    float inv = rsqrtf(fmaxf(s, 1e-24f));
    // match reference: 1/max(sqrt(s),1e-12). For realistic s these agree;
    // write the precise form to be safe:
    inv = 1.0f / fmaxf(sqrtf(s), 1e-12f);
    if (lane == 0) g_inv_nrm[warp] = inv;

    // normalized fp16 row: lane writes 4 halves (8B) -> 256 B per row
    __half2 h0 = __floats2half2_rn(a.x * inv, a.y * inv);
    __half2 h1 = __floats2half2_rn(a.z * inv, a.w * inv);
    uint2 packed;
    packed.x = *reinterpret_cast<unsigned*>(&h0);
    packed.y = *reinterpret_cast<unsigned*>(&h1);
    reinterpret_cast<uint2*>(g_fn + (size_t)warp * D_FEAT)[lane] = packed;
}

// ---------------------------------------------------------------------------
// Kernel 2: per-edge cosine sim (warp per edge).
// fp16 pre-pass (256 B/row); if the fp16 sim could pass the threshold,
// recompute exactly in fp32 from the original features. All stored sims are
// exact fp32; fp16 only vetoes edges safely below threshold.
// ---------------------------------------------------------------------------
__global__ void sim_kernel(const int* __restrict__ ei,
                           const float* __restrict__ feat,
                           int n_edge) {
    int warp = (blockIdx.x * blockDim.x + threadIdx.x) >> 5;
    int lane = threadIdx.x & 31;
    if (warp >= n_edge) return;

    int stride = g_idx_stride;
    int r = ei[(long long)warp * stride];
    int c = ei[((long long)n_edge + warp) * stride];

    // fp16 gather: 32 lanes * 8 B = 256 B per row
    uint2 pa = reinterpret_cast<const uint2*>(g_fn + (size_t)r * D_FEAT)[lane];
    uint2 pb = reinterpret_cast<const uint2*>(g_fn + (size_t)c * D_FEAT)[lane];
    float2 a0 = __half22float2(*reinterpret_cast<__half2*>(&pa.x));
    float2 a1 = __half22float2(*reinterpret_cast<__half2*>(&pa.y));
    float2 b0 = __half22float2(*reinterpret_cast<__half2*>(&pb.x));
    float2 b1 = __half22float2(*reinterpret_cast<__half2*>(&pb.y));
    float acc = a0.x * b0.x + a0.y * b0.y + a1.x * b1.x + a1.y * b1.y;
    #pragma unroll
    for (int off = 16; off > 0; off >>= 1)
        acc += __shfl_xor_sync(0xFFFFFFFFu, acc, off);   // all lanes have sim16

    float s = 0.0f;
    if (acc >= SIM_THRESH - BAND) {
        // exact fp32 recompute (whole warp, no divergence within the warp)
        const float4* FR = reinterpret_cast<const float4*>(feat + (size_t)r * D_FEAT);
        const float4* FC = reinterpret_cast<const float4*>(feat + (size_t)c * D_FEAT);
        float4 A = FR[lane];
        float4 B = FC[lane];
        float d = A.x * B.x + A.y * B.y + A.z * B.z + A.w * B.w;
        #pragma unroll
        for (int off = 16; off > 0; off >>= 1)
            d += __shfl_xor_sync(0xFFFFFFFFu, d, off);
        float sx = d * g_inv_nrm[r] * g_inv_nrm[c];
        s = (sx < SIM_THRESH) ? 0.0f : sx;
    }

    if (lane == 0) {
        g_sim[warp] = s;
        if (s != 0.0f) atomicAdd(&g_row_sum[r], s);  // s >= 0 after threshold
    }
}

// ---------------------------------------------------------------------------
// Kernel 3: finish — normalize, exp, gate blend, clamp. ILP=4 per thread to
// hide the random row_sum gather latency.
// (inputs guarantee row != col, so the lam/diagonal term is always zero)
// ---------------------------------------------------------------------------
__global__ void finish_kernel(const int* __restrict__ ei,
                              const float* __restrict__ edge_weight,
                              const float* __restrict__ gate,
                              float* __restrict__ out,
                              int n_edge, int seg) {
    int t = blockIdx.x * blockDim.x + threadIdx.x;
    if (t >= seg) return;
    int stride = g_idx_stride;
    float g = __ldg(gate);
    float one_m_g = 1.0f - g;

    int   e[4];
    int   r[4];
    float rs[4], sm[4], w[4];
    #pragma unroll
    for (int k = 0; k < 4; k++) e[k] = t + k * seg;

    #pragma unroll
    for (int k = 0; k < 4; k++)
        r[k] = (e[k] < n_edge) ? ei[(long long)e[k] * stride] : 0;
    #pragma unroll
    for (int k = 0; k < 4; k++) rs[k] = g_row_sum[r[k]];
    #pragma unroll
    for (int k = 0; k < 4; k++) sm[k] = (e[k] < n_edge) ? g_sim[e[k]] : 0.0f;
    #pragma unroll
    for (int k = 0; k < 4; k++) w[k]  = (e[k] < n_edge) ? edge_weight[e[k]] : 0.0f;

    #pragma unroll
    for (int k = 0; k < 4; k++) {
        if (e[k] >= n_edge) continue;
        float denom = (rs[k] > 0.0f) ? rs[k] : 1.0f;
        float att = expf(sm[k] / denom);
        out[e[k]] = fmaxf(g * w[k] + one_m_g * att, 0.0f);
    }
}

// ---------------------------------------------------------------------------
extern "C" void kernel_launch(void* const* d_in, const int* in_sizes, int n_in,
                              void* d_out, int out_size) {
    const int*   ei   = (const int*)d_in[0];     // [2, E] int32 (or int64, detected)
    const float* ew   = (const float*)d_in[1];   // [E]
    const float* feat = (const float*)d_in[2];   // [N, D]
    const float* gate = (const float*)d_in[3];   // [1]

    int n_edge = in_sizes[1];
    int n_node = in_sizes[2] / D_FEAT;

    // Kernel 1: warp per node (also zeroes row_sum + dtype detection)
    {
        int blocks = (n_node * 32 + 255) / 256;
        norm_kernel<<<blocks, 256>>>(feat, ei, n_node);
    }
    // Kernel 2: warp per edge
    {
        long long total = (long long)n_edge * 32;
        int blocks = (int)((total + 255) / 256);
        sim_kernel<<<blocks, 256>>>(ei, feat, n_edge);
    }
    // Kernel 3: 4 edges per thread
    {
        int seg = (n_edge + 3) / 4;
        int blocks = (seg + 255) / 256;
        finish_kernel<<<blocks, 256>>>(ei, ew, gate, (float*)d_out, n_edge, seg);
    }
}

// round 4
// speedup vs baseline: 1.3574x; 1.3574x over previous
#include <cuda_runtime.h>
#include <cuda_fp16.h>

// Problem constants (from reference): N=50000, D=128, E=625000
#define N_NODE   50000
#define D_FEAT   128
#define N_EDGE_MAX 625000
#define SIM_THRESH 0.1f
#define BAND 2.0e-3f   // rigorous fp16 dot error bound is ~1.1e-3; 2e-3 is safe

// Scratch (device globals — no allocation allowed in kernel_launch)
__device__ float g_inv_nrm[N_NODE];           // 1 / max(||f||, 1e-12)
__device__ float g_row_sum[N_NODE];           // L1 row sums of thresholded sim
__device__ float g_sim[N_EDGE_MAX];           // thresholded per-edge sim (exact fp32)
__device__ int   g_idx_stride;                // 1 = int32 edge_index, 2 = int64
__device__ __align__(16) __half g_fn[(size_t)N_NODE * D_FEAT];  // normalized fp16 feats

// ---------------------------------------------------------------------------
// Kernel 1: per-node inverse norm — 2 nodes per warp (interleaved reductions),
// writes normalized fp16 features, zeroes row_sum, detects edge_index dtype.
// ---------------------------------------------------------------------------
__global__ void norm_kernel(const float* __restrict__ feat,
                            const int* __restrict__ ei,
                            int n_node) {
    int tid  = blockIdx.x * blockDim.x + threadIdx.x;
    int warp = tid >> 5;
    int lane = threadIdx.x & 31;

    if (tid == 0) {
        // int64 little-endian => odd 32-bit words of first 8 indices all zero
        bool all_hi_zero = true;
        #pragma unroll
        for (int i = 0; i < 8; i++)
            if (ei[2 * i + 1] != 0) all_hi_zero = false;
        g_idx_stride = all_hi_zero ? 2 : 1;
    }
    if (tid < n_node) g_row_sum[tid] = 0.0f;

    int n0 = warp * 2;
    int n1 = warp * 2 + 1;
    if (n0 >= n_node) return;
    bool has1 = (n1 < n_node);

    const float4* F = reinterpret_cast<const float4*>(feat);
    float4 a0 = F[(size_t)n0 * 32 + lane];
    float4 a1 = has1 ? F[(size_t)n1 * 32 + lane] : make_float4(0, 0, 0, 0);

    float s0 = a0.x * a0.x + a0.y * a0.y + a0.z * a0.z + a0.w * a0.w;
    float s1 = a1.x * a1.x + a1.y * a1.y + a1.z * a1.z + a1.w * a1.w;
    #pragma unroll
    for (int off = 16; off > 0; off >>= 1) {
        s0 += __shfl_xor_sync(0xFFFFFFFFu, s0, off);
        s1 += __shfl_xor_sync(0xFFFFFFFFu, s1, off);
    }

    float inv0 = 1.0f / fmaxf(sqrtf(s0), 1e-12f);
    float inv1 = 1.0f / fmaxf(sqrtf(s1), 1e-12f);
    if (lane == 0) {
        g_inv_nrm[n0] = inv0;
        if (has1) g_inv_nrm[n1] = inv1;
    }

    // normalized fp16 rows: lane writes 4 halves (8 B) per node
    {
        __half2 h0 = __floats2half2_rn(a0.x * inv0, a0.y * inv0);
        __half2 h1 = __floats2half2_rn(a0.z * inv0, a0.w * inv0);
        uint2 p;
        p.x = *reinterpret_cast<unsigned*>(&h0);
        p.y = *reinterpret_cast<unsigned*>(&h1);
        reinterpret_cast<uint2*>(g_fn + (size_t)n0 * D_FEAT)[lane] = p;
    }
    if (has1) {
        __half2 h0 = __floats2half2_rn(a1.x * inv1, a1.y * inv1);
        __half2 h1 = __floats2half2_rn(a1.z * inv1, a1.w * inv1);
        uint2 p;
        p.x = *reinterpret_cast<unsigned*>(&h0);
        p.y = *reinterpret_cast<unsigned*>(&h1);
        reinterpret_cast<uint2*>(g_fn + (size_t)n1 * D_FEAT)[lane] = p;
    }
}

// ---------------------------------------------------------------------------
// Kernel 2: 4 edges per warp. All 8 fp16 row gathers batched up-front (MLP 8),
// 4 interleaved shuffle-reduction trees. Edges whose fp16 sim could pass the
// threshold (~14%) are recomputed exactly in fp32 (warp-uniform branch).
// ---------------------------------------------------------------------------
__global__ void sim_kernel(const int* __restrict__ ei,
                           const float* __restrict__ feat,
                           int n_edge) {
    int warp = (blockIdx.x * blockDim.x + threadIdx.x) >> 5;
    int lane = threadIdx.x & 31;
    long long e_base = (long long)warp * 4;
    if (e_base >= n_edge) return;
    int stride = g_idx_stride;

    int r[4], c[4];
    #pragma unroll
    for (int k = 0; k < 4; k++) {
        long long e = e_base + k;
        if (e < n_edge) {
            r[k] = ei[e * stride];
            c[k] = ei[((long long)n_edge + e) * stride];
        } else { r[k] = 0; c[k] = 0; }
    }

    // batched fp16 gathers: 8 independent LDG.64 (256 B per row warp-wide)
    uint2 pa[4], pb[4];
    #pragma unroll
    for (int k = 0; k < 4; k++) {
        pa[k] = reinterpret_cast<const uint2*>(g_fn + (size_t)r[k] * D_FEAT)[lane];
        pb[k] = reinterpret_cast<const uint2*>(g_fn + (size_t)c[k] * D_FEAT)[lane];
    }

    float acc[4];
    #pragma unroll
    for (int k = 0; k < 4; k++) {
        float2 a0 = __half22float2(*reinterpret_cast<__half2*>(&pa[k].x));
        float2 a1 = __half22float2(*reinterpret_cast<__half2*>(&pa[k].y));
        float2 b0 = __half22float2(*reinterpret_cast<__half2*>(&pb[k].x));
        float2 b1 = __half22float2(*reinterpret_cast<__half2*>(&pb[k].y));
        acc[k] = a0.x * b0.x + a0.y * b0.y + a1.x * b1.x + a1.y * b1.y;
    }
    // interleaved reduction trees (independent SHFL chains pipeline)
    #pragma unroll
    for (int off = 16; off > 0; off >>= 1) {
        #pragma unroll
        for (int k = 0; k < 4; k++)
            acc[k] += __shfl_xor_sync(0xFFFFFFFFu, acc[k], off);
    }

    const float4* F = reinterpret_cast<const float4*>(feat);
    #pragma unroll
    for (int k = 0; k < 4; k++) {
        long long e = e_base + k;
        if (e >= n_edge) break;
        float s = 0.0f;
        if (acc[k] >= SIM_THRESH - BAND) {        // warp-uniform predicate
            // exact fp32 recompute from original features
            float4 A = F[(size_t)r[k] * 32 + lane];
            float4 B = F[(size_t)c[k] * 32 + lane];
            float d = A.x * B.x + A.y * B.y + A.z * B.z + A.w * B.w;
            #pragma unroll
            for (int off = 16; off > 0; off >>= 1)
                d += __shfl_xor_sync(0xFFFFFFFFu, d, off);
            float sx = d * g_inv_nrm[r[k]] * g_inv_nrm[c[k]];
            s = (sx < SIM_THRESH) ? 0.0f : sx;
        }
        if (lane == 0) {
            g_sim[e] = s;
            if (s != 0.0f) atomicAdd(&g_row_sum[r[k]], s);  // s >= 0 after threshold
        }
    }
}

// ---------------------------------------------------------------------------
// Kernel 3: finish — normalize, exp, gate blend, clamp. ILP=4 per thread.
// (inputs guarantee row != col, so the lam/diagonal term is always zero)
// ---------------------------------------------------------------------------
__global__ void finish_kernel(const int* __restrict__ ei,
                              const float* __restrict__ edge_weight,
                              const float* __restrict__ gate,
                              float* __restrict__ out,
                              int n_edge, int seg) {
    int t = blockIdx.x * blockDim.x + threadIdx.x;
    if (t >= seg) return;
    int stride = g_idx_stride;
    float g = __ldg(gate);
    float one_m_g = 1.0f - g;

    int   e[4];
    int   r[4];
    float rs[4], sm[4], w[4];
    #pragma unroll
    for (int k = 0; k < 4; k++) e[k] = t + k * seg;

    #pragma unroll
    for (int k = 0; k < 4; k++)
        r[k] = (e[k] < n_edge) ? ei[(long long)e[k] * stride] : 0;
    #pragma unroll
    for (int k = 0; k < 4; k++) rs[k] = g_row_sum[r[k]];
    #pragma unroll
    for (int k = 0; k < 4; k++) sm[k] = (e[k] < n_edge) ? g_sim[e[k]] : 0.0f;
    #pragma unroll
    for (int k = 0; k < 4; k++) w[k]  = (e[k] < n_edge) ? edge_weight[e[k]] : 0.0f;

    #pragma unroll
    for (int k = 0; k < 4; k++) {
        if (e[k] >= n_edge) continue;
        float denom = (rs[k] > 0.0f) ? rs[k] : 1.0f;
        float att = expf(sm[k] / denom);
        out[e[k]] = fmaxf(g * w[k] + one_m_g * att, 0.0f);
    }
}

// ---------------------------------------------------------------------------
extern "C" void kernel_launch(void* const* d_in, const int* in_sizes, int n_in,
                              void* d_out, int out_size) {
    const int*   ei   = (const int*)d_in[0];     // [2, E] int32 (or int64, detected)
    const float* ew   = (const float*)d_in[1];   // [E]
    const float* feat = (const float*)d_in[2];   // [N, D]
    const float* gate = (const float*)d_in[3];   // [1]

    int n_edge = in_sizes[1];
    int n_node = in_sizes[2] / D_FEAT;

    // Kernel 1: 2 nodes per warp (also zeroes row_sum + dtype detection)
    {
        int n_warps = (n_node + 1) / 2;
        long long total = (long long)n_warps * 32;
        int blocks = (int)((total + 255) / 256);
        // ensure enough threads to zero row_sum too
        long long zero_blocks = ((long long)n_node + 255) / 256;
        if (zero_blocks > blocks) blocks = (int)zero_blocks;
        norm_kernel<<<blocks, 256>>>(feat, ei, n_node);
    }
    // Kernel 2: 4 edges per warp
    {
        int n_warps = (n_edge + 3) / 4;
        long long total = (long long)n_warps * 32;
        int blocks = (int)((total + 255) / 256);
        sim_kernel<<<blocks, 256>>>(ei, feat, n_edge);
    }
    // Kernel 3: 4 edges per thread
    {
        int seg = (n_edge + 3) / 4;
        int blocks = (seg + 255) / 256;
        finish_kernel<<<blocks, 256>>>(ei, ew, gate, (float*)d_out, n_edge, seg);
    }
}

// round 5
// speedup vs baseline: 1.4543x; 1.0714x over previous
#include <cuda_runtime.h>
#include <cuda_fp16.h>

// Problem constants (from reference): N=50000, D=128, E=625000
#define N_NODE   50000
#define D_FEAT   128
#define N_EDGE_MAX 625000
#define SIM_THRESH 0.1f
#define BAND 2.0e-3f   // rigorous fp16 dot error bound is ~1.1e-3; 2e-3 is safe

// Scratch (device globals — no allocation allowed in kernel_launch)
__device__ float g_inv_nrm[N_NODE];           // 1 / max(||f||, 1e-12)
__device__ float g_row_sum[N_NODE];           // L1 row sums of thresholded sim
__device__ float g_sim[N_EDGE_MAX];           // thresholded per-edge sim (exact fp32)
__device__ int   g_idx_stride;                // 1 = int32 edge_index, 2 = int64
__device__ __align__(16) __half g_fn[(size_t)N_NODE * D_FEAT];  // normalized fp16 feats

// ---------------------------------------------------------------------------
// Kernel 1: per-node inverse norm — 4 nodes per warp, front-batched loads,
// writes normalized fp16 features, zeroes row_sum, detects edge_index dtype.
// ---------------------------------------------------------------------------
__global__ void norm_kernel(const float* __restrict__ feat,
                            const int* __restrict__ ei,
                            int n_node) {
    int tid  = blockIdx.x * blockDim.x + threadIdx.x;
    int warp = tid >> 5;
    int lane = threadIdx.x & 31;

    if (tid == 0) {
        // int64 little-endian => odd 32-bit words of first 8 indices all zero
        bool all_hi_zero = true;
        #pragma unroll
        for (int i = 0; i < 8; i++)
            if (ei[2 * i + 1] != 0) all_hi_zero = false;
        g_idx_stride = all_hi_zero ? 2 : 1;
    }
    if (tid < n_node) g_row_sum[tid] = 0.0f;

    int nb = warp * 4;
    if (nb >= n_node) return;

    const float4* F = reinterpret_cast<const float4*>(feat);
    float4 a[4];
    #pragma unroll
    for (int k = 0; k < 4; k++) {
        int n = nb + k;
        a[k] = (n < n_node) ? F[(size_t)n * 32 + lane] : make_float4(0, 0, 0, 0);
    }

    float s[4];
    #pragma unroll
    for (int k = 0; k < 4; k++)
        s[k] = a[k].x * a[k].x + a[k].y * a[k].y + a[k].z * a[k].z + a[k].w * a[k].w;
    #pragma unroll
    for (int off = 16; off > 0; off >>= 1) {
        #pragma unroll
        for (int k = 0; k < 4; k++)
            s[k] += __shfl_xor_sync(0xFFFFFFFFu, s[k], off);
    }

    #pragma unroll
    for (int k = 0; k < 4; k++) {
        int n = nb + k;
        if (n >= n_node) break;
        float inv = 1.0f / fmaxf(sqrtf(s[k]), 1e-12f);
        if (lane == 0) g_inv_nrm[n] = inv;
        __half2 h0 = __floats2half2_rn(a[k].x * inv, a[k].y * inv);
        __half2 h1 = __floats2half2_rn(a[k].z * inv, a[k].w * inv);
        uint2 p;
        p.x = *reinterpret_cast<unsigned*>(&h0);
        p.y = *reinterpret_cast<unsigned*>(&h1);
        reinterpret_cast<uint2*>(g_fn + (size_t)n * D_FEAT)[lane] = p;
    }
}

// ---------------------------------------------------------------------------
// Kernel 2: 8 edges per warp — 16 lanes per edge, LDG.128 fp16 gathers
// (8 front-batched loads = MLP 8 x 128B), 4-level half-warp reductions.
// Edges whose fp16 sim could pass the threshold (~14%) are recomputed exactly
// in fp32 (half-warp-uniform branch, per-half shuffle masks).
// ---------------------------------------------------------------------------
__global__ void sim_kernel(const int* __restrict__ ei,
                           const float* __restrict__ feat,
                           int n_edge) {
    int warp = (blockIdx.x * blockDim.x + threadIdx.x) >> 5;
    int lane = threadIdx.x & 31;
    int half = lane >> 4;          // 0 or 1
    int hl   = lane & 15;          // lane within half-warp
    unsigned hmask = half ? 0xFFFF0000u : 0x0000FFFFu;

    long long e_base = (long long)warp * 8;
    if (e_base >= n_edge) return;
    int stride = g_idx_stride;

    // Each half-warp owns edges e_base + 2k + half, k=0..3
    int r[4], c[4];
    bool valid[4];
    #pragma unroll
    for (int k = 0; k < 4; k++) {
        long long e = e_base + 2 * k + half;
        valid[k] = (e < n_edge);
        if (valid[k]) {
            r[k] = ei[e * stride];
            c[k] = ei[((long long)n_edge + e) * stride];
        } else { r[k] = 0; c[k] = 0; }
    }

    // batched fp16 gathers: 8 independent LDG.128 (16 lanes x 16B = 256B/row)
    uint4 pa[4], pb[4];
    #pragma unroll
    for (int k = 0; k < 4; k++) {
        pa[k] = reinterpret_cast<const uint4*>(g_fn + (size_t)r[k] * D_FEAT)[hl];
        pb[k] = reinterpret_cast<const uint4*>(g_fn + (size_t)c[k] * D_FEAT)[hl];
    }

    float acc[4];
    #pragma unroll
    for (int k = 0; k < 4; k++) {
        const __half2* ha = reinterpret_cast<const __half2*>(&pa[k]);
        const __half2* hb = reinterpret_cast<const __half2*>(&pb[k]);
        float d = 0.0f;
        #pragma unroll
        for (int j = 0; j < 4; j++) {
            float2 x = __half22float2(ha[j]);
            float2 y = __half22float2(hb[j]);
            d += x.x * y.x + x.y * y.y;
        }
        acc[k] = d;
    }
    // interleaved 4-level half-warp reductions
    #pragma unroll
    for (int off = 8; off > 0; off >>= 1) {
        #pragma unroll
        for (int k = 0; k < 4; k++)
            acc[k] += __shfl_xor_sync(hmask, acc[k], off);
    }

    const float4* F = reinterpret_cast<const float4*>(feat);
    #pragma unroll
    for (int k = 0; k < 4; k++) {
        if (!valid[k]) continue;
        long long e = e_base + 2 * k + half;
        float s = 0.0f;
        if (acc[k] >= SIM_THRESH - BAND) {      // uniform within half-warp
            // exact fp32 recompute: 16 lanes x 2 float4 = 512 B per row
            const float4* FR = F + (size_t)r[k] * 32;
            const float4* FC = F + (size_t)c[k] * 32;
            float4 A0 = FR[hl],      B0 = FC[hl];
            float4 A1 = FR[hl + 16], B1 = FC[hl + 16];
            float d = A0.x * B0.x + A0.y * B0.y + A0.z * B0.z + A0.w * B0.w
                    + A1.x * B1.x + A1.y * B1.y + A1.z * B1.z + A1.w * B1.w;
            #pragma unroll
            for (int off = 8; off > 0; off >>= 1)
                d += __shfl_xor_sync(hmask, d, off);
            float sx = d * g_inv_nrm[r[k]] * g_inv_nrm[c[k]];
            s = (sx < SIM_THRESH) ? 0.0f : sx;
        }
        if (hl == 0) {
            g_sim[e] = s;
            if (s != 0.0f) atomicAdd(&g_row_sum[r[k]], s);  // s >= 0 after threshold
        }
    }
}

// ---------------------------------------------------------------------------
// Kernel 3: finish — normalize, exp, gate blend, clamp. ILP=4 per thread.
// (inputs guarantee row != col, so the lam/diagonal term is always zero)
// ---------------------------------------------------------------------------
__global__ void finish_kernel(const int* __restrict__ ei,
                              const float* __restrict__ edge_weight,
                              const float* __restrict__ gate,
                              float* __restrict__ out,
                              int n_edge, int seg) {
    int t = blockIdx.x * blockDim.x + threadIdx.x;
    if (t >= seg) return;
    int stride = g_idx_stride;
    float g = __ldg(gate);
    float one_m_g = 1.0f - g;

    int   e[4];
    int   r[4];
    float rs[4], sm[4], w[4];
    #pragma unroll
    for (int k = 0; k < 4; k++) e[k] = t + k * seg;

    #pragma unroll
    for (int k = 0; k < 4; k++)
        r[k] = (e[k] < n_edge) ? ei[(long long)e[k] * stride] : 0;
    #pragma unroll
    for (int k = 0; k < 4; k++) rs[k] = g_row_sum[r[k]];
    #pragma unroll
    for (int k = 0; k < 4; k++) sm[k] = (e[k] < n_edge) ? g_sim[e[k]] : 0.0f;
    #pragma unroll
    for (int k = 0; k < 4; k++) w[k]  = (e[k] < n_edge) ? edge_weight[e[k]] : 0.0f;

    #pragma unroll
    for (int k = 0; k < 4; k++) {
        if (e[k] >= n_edge) continue;
        float denom = (rs[k] > 0.0f) ? rs[k] : 1.0f;
        float att = expf(sm[k] / denom);
        out[e[k]] = fmaxf(g * w[k] + one_m_g * att, 0.0f);
    }
}

// ---------------------------------------------------------------------------
extern "C" void kernel_launch(void* const* d_in, const int* in_sizes, int n_in,
                              void* d_out, int out_size) {
    const int*   ei   = (const int*)d_in[0];     // [2, E] int32 (or int64, detected)
    const float* ew   = (const float*)d_in[1];   // [E]
    const float* feat = (const float*)d_in[2];   // [N, D]
    const float* gate = (const float*)d_in[3];   // [1]

    int n_edge = in_sizes[1];
    int n_node = in_sizes[2] / D_FEAT;

    // Kernel 1: 4 nodes per warp (also zeroes row_sum + dtype detection)
    {
        int n_warps = (n_node + 3) / 4;
        long long total = (long long)n_warps * 32;
        int blocks = (int)((total + 255) / 256);
        long long zero_blocks = ((long long)n_node + 255) / 256;
        if (zero_blocks > blocks) blocks = (int)zero_blocks;
        norm_kernel<<<blocks, 256>>>(feat, ei, n_node);
    }
    // Kernel 2: 8 edges per warp
    {
        int n_warps = (n_edge + 7) / 8;
        long long total = (long long)n_warps * 32;
        int blocks = (int)((total + 255) / 256);
        sim_kernel<<<blocks, 256>>>(ei, feat, n_edge);
    }
    // Kernel 3: 4 edges per thread
    {
        int seg = (n_edge + 3) / 4;
        int blocks = (seg + 255) / 256;
        finish_kernel<<<blocks, 256>>>(ei, ew, gate, (float*)d_out, n_edge, seg);
    }
}

// round 6
// speedup vs baseline: 1.5077x; 1.0367x over previous
#include <cuda_runtime.h>
#include <cuda_fp16.h>

// Problem constants (from reference): N=50000, D=128, E=625000
#define N_NODE   50000
#define D_FEAT   128
#define N_EDGE_MAX 625000
#define SIM_THRESH 0.1f
#define BAND 2.0e-3f   // rigorous fp16 dot error bound is ~1.1e-3; 2e-3 is safe

// Scratch (device globals — no allocation allowed in kernel_launch)
__device__ float g_inv_nrm[N_NODE];           // 1 / max(||f||, 1e-12)
__device__ float g_row_sum[N_NODE];           // L1 row sums of thresholded sim
__device__ float g_sim[N_EDGE_MAX];           // thresholded per-edge sim (exact fp32)
__device__ __align__(16) __half g_fn[(size_t)N_NODE * D_FEAT];  // normalized fp16 feats

// ---------------------------------------------------------------------------
// Kernel 1: per-node inverse norm — 4 nodes per warp, front-batched loads,
// writes normalized fp16 features, zeroes row_sum. Triggers dependent (sim)
// launch before its store phase (PDL).
// ---------------------------------------------------------------------------
__global__ void norm_kernel(const float* __restrict__ feat, int n_node) {
    int tid  = blockIdx.x * blockDim.x + threadIdx.x;
    int warp = tid >> 5;
    int lane = threadIdx.x & 31;

    if (tid < n_node) g_row_sum[tid] = 0.0f;

    int nb = warp * 4;
    if (nb >= n_node) return;   // exited CTAs count as triggered

    const float4* F = reinterpret_cast<const float4*>(feat);
    float4 a[4];
    #pragma unroll
    for (int k = 0; k < 4; k++) {
        int n = nb + k;
        a[k] = (n < n_node) ? F[(size_t)n * 32 + lane] : make_float4(0, 0, 0, 0);
    }

    float s[4];
    #pragma unroll
    for (int k = 0; k < 4; k++)
        s[k] = a[k].x * a[k].x + a[k].y * a[k].y + a[k].z * a[k].z + a[k].w * a[k].w;
    #pragma unroll
    for (int off = 16; off > 0; off >>= 1) {
        #pragma unroll
        for (int k = 0; k < 4; k++)
            s[k] += __shfl_xor_sync(0xFFFFFFFFu, s[k], off);
    }

    // let the sim grid begin its (independent) prologue while we store
    cudaTriggerProgrammaticLaunchCompletion();

    #pragma unroll
    for (int k = 0; k < 4; k++) {
        int n = nb + k;
        if (n >= n_node) break;
        float inv = 1.0f / fmaxf(sqrtf(s[k]), 1e-12f);
        if (lane == 0) g_inv_nrm[n] = inv;
        __half2 h0 = __floats2half2_rn(a[k].x * inv, a[k].y * inv);
        __half2 h1 = __floats2half2_rn(a[k].z * inv, a[k].w * inv);
        uint2 p;
        p.x = *reinterpret_cast<unsigned*>(&h0);
        p.y = *reinterpret_cast<unsigned*>(&h1);
        reinterpret_cast<uint2*>(g_fn + (size_t)n * D_FEAT)[lane] = p;
    }
}

// ---------------------------------------------------------------------------
// Kernel 2: 8 edges per warp — 16 lanes per edge, LDG.128 fp16 gathers,
// coalesced+shuffled index loads, pair-batched fp32 recompute for edges whose
// fp16 sim could pass the threshold (~14%). PDL secondary: prefetches indices
// before cudaGridDependencySynchronize().
// ---------------------------------------------------------------------------
__global__ void sim_kernel(const int* __restrict__ ei,
                           const float* __restrict__ feat,
                           int n_edge) {
    int warp = (blockIdx.x * blockDim.x + threadIdx.x) >> 5;
    int lane = threadIdx.x & 31;
    int half = lane >> 4;          // 0 or 1
    int hl   = lane & 15;          // lane within half-warp
    unsigned hmask = half ? 0xFFFF0000u : 0x0000FFFFu;

    long long e_base = (long long)warp * 8;
    if (e_base >= n_edge) { cudaGridDependencySynchronize(); return; }

    // ---- PDL prologue: edge indices are harness inputs, independent of norm
    int v = 0;
    {
        long long e = e_base + (lane & 7);
        if (lane < 16 && e < n_edge) {
            long long pos = (lane & 8) ? (long long)n_edge + e : e;
            v = ei[pos];
        }
    }
    int r[4], c[4];
    bool valid[4];
    #pragma unroll
    for (int k = 0; k < 4; k++) {
        int src = 2 * k + half;                       // this half-warp's edge
        r[k] = __shfl_sync(0xFFFFFFFFu, v, src);
        c[k] = __shfl_sync(0xFFFFFFFFu, v, 8 + src);
        valid[k] = (e_base + src) < n_edge;
    }

    // ---- wait for norm_kernel's writes (g_fn, g_inv_nrm, g_row_sum)
    cudaGridDependencySynchronize();

    // batched fp16 gathers: 8 independent LDG.128 (16 lanes x 16B = 256B/row)
    uint4 pa[4], pb[4];
    #pragma unroll
    for (int k = 0; k < 4; k++) {
        pa[k] = reinterpret_cast<const uint4*>(g_fn + (size_t)r[k] * D_FEAT)[hl];
        pb[k] = reinterpret_cast<const uint4*>(g_fn + (size_t)c[k] * D_FEAT)[hl];
    }

    float acc[4];
    #pragma unroll
    for (int k = 0; k < 4; k++) {
        const __half2* ha = reinterpret_cast<const __half2*>(&pa[k]);
        const __half2* hb = reinterpret_cast<const __half2*>(&pb[k]);
        float d = 0.0f;
        #pragma unroll
        for (int j = 0; j < 4; j++) {
            float2 x = __half22float2(ha[j]);
            float2 y = __half22float2(hb[j]);
            d += x.x * y.x + x.y * y.y;
        }
        acc[k] = d;
    }
    // interleaved 4-level half-warp reductions
    #pragma unroll
    for (int off = 8; off > 0; off >>= 1) {
        #pragma unroll
        for (int k = 0; k < 4; k++)
            acc[k] += __shfl_xor_sync(hmask, acc[k], off);
    }

    bool need[4];
    #pragma unroll
    for (int k = 0; k < 4; k++)
        need[k] = valid[k] && (acc[k] >= SIM_THRESH - BAND);  // half-warp uniform

    float s[4] = {0.0f, 0.0f, 0.0f, 0.0f};
    const float4* F = reinterpret_cast<const float4*>(feat);
    #pragma unroll
    for (int kk = 0; kk < 4; kk += 2) {
        float4 A0[2], A1[2], B0[2], B1[2];
        #pragma unroll
        for (int j = 0; j < 2; j++) {
            int k = kk + j;
            if (need[k]) {   // batch both edges' loads before either reduction
                const float4* FR = F + (size_t)r[k] * 32;
                const float4* FC = F + (size_t)c[k] * 32;
                A0[j] = FR[hl];      B0[j] = FC[hl];
                A1[j] = FR[hl + 16]; B1[j] = FC[hl + 16];
            }
        }
        #pragma unroll
        for (int j = 0; j < 2; j++) {
            int k = kk + j;
            if (need[k]) {
                float d = A0[j].x * B0[j].x + A0[j].y * B0[j].y
                        + A0[j].z * B0[j].z + A0[j].w * B0[j].w
                        + A1[j].x * B1[j].x + A1[j].y * B1[j].y
                        + A1[j].z * B1[j].z + A1[j].w * B1[j].w;
                #pragma unroll
                for (int off = 8; off > 0; off >>= 1)
                    d += __shfl_xor_sync(hmask, d, off);
                float sx = d * g_inv_nrm[r[k]] * g_inv_nrm[c[k]];
                s[k] = (sx < SIM_THRESH) ? 0.0f : sx;
            }
        }
    }

    // let the finish grid begin its (independent) prologue
    cudaTriggerProgrammaticLaunchCompletion();

    if (hl == 0) {
        #pragma unroll
        for (int k = 0; k < 4; k++) {
            if (!valid[k]) continue;
            long long e = e_base + 2 * k + half;
            g_sim[e] = s[k];
            if (s[k] != 0.0f) atomicAdd(&g_row_sum[r[k]], s[k]);  // s >= 0
        }
    }
}

// ---------------------------------------------------------------------------
// Kernel 3: finish — normalize, exp, gate blend, clamp. ILP=4 per thread.
// PDL secondary: prefetches ei/ew/gate before the dependency sync.
// (inputs guarantee row != col, so the lam/diagonal term is always zero)
// ---------------------------------------------------------------------------
__global__ void finish_kernel(const int* __restrict__ ei,
                              const float* __restrict__ edge_weight,
                              const float* __restrict__ gate,
                              float* __restrict__ out,
                              int n_edge, int seg) {
    int t = blockIdx.x * blockDim.x + threadIdx.x;
    if (t >= seg) { cudaGridDependencySynchronize(); return; }

    int   e[4];
    int   r[4];
    float w[4];
    #pragma unroll
    for (int k = 0; k < 4; k++) e[k] = t + k * seg;
    #pragma unroll
    for (int k = 0; k < 4; k++)
        r[k] = (e[k] < n_edge) ? ei[e[k]] : 0;
    #pragma unroll
    for (int k = 0; k < 4; k++)
        w[k] = (e[k] < n_edge) ? edge_weight[e[k]] : 0.0f;
    float g = __ldg(gate);
    float one_m_g = 1.0f - g;

    // ---- wait for sim_kernel's writes (g_sim, g_row_sum)
    cudaGridDependencySynchronize();

    float rs[4], sm[4];
    #pragma unroll
    for (int k = 0; k < 4; k++) rs[k] = g_row_sum[r[k]];
    #pragma unroll
    for (int k = 0; k < 4; k++) sm[k] = (e[k] < n_edge) ? g_sim[e[k]] : 0.0f;

    #pragma unroll
    for (int k = 0; k < 4; k++) {
        if (e[k] >= n_edge) continue;
        float denom = (rs[k] > 0.0f) ? rs[k] : 1.0f;
        float att = expf(sm[k] / denom);
        out[e[k]] = fmaxf(g * w[k] + one_m_g * att, 0.0f);
    }
}

// ---------------------------------------------------------------------------
extern "C" void kernel_launch(void* const* d_in, const int* in_sizes, int n_in,
                              void* d_out, int out_size) {
    const int*   ei   = (const int*)d_in[0];     // [2, E] int32 (verified: int64 read crashed)
    const float* ew   = (const float*)d_in[1];   // [E]
    const float* feat = (const float*)d_in[2];   // [N, D]
    const float* gate = (const float*)d_in[3];   // [1]

    int n_edge = in_sizes[1];
    int n_node = in_sizes[2] / D_FEAT;

    // Kernel 1: 4 nodes per warp (also zeroes row_sum)
    {
        int n_warps = (n_node + 3) / 4;
        long long total = (long long)n_warps * 32;
        int blocks = (int)((total + 255) / 256);
        long long zero_blocks = ((long long)n_node + 255) / 256;
        if (zero_blocks > blocks) blocks = (int)zero_blocks;
        norm_kernel<<<blocks, 256>>>(feat, n_node);
    }

    cudaLaunchAttribute pdl_attr[1];
    pdl_attr[0].id = cudaLaunchAttributeProgrammaticStreamSerialization;
    pdl_attr[0].val.programmaticStreamSerializationAllowed = 1;

    // Kernel 2: 8 edges per warp (PDL secondary of norm)
    {
        int n_warps = (n_edge + 7) / 8;
        long long total = (long long)n_warps * 32;
        cudaLaunchConfig_t cfg = {};
        cfg.gridDim  = dim3((unsigned)((total + 255) / 256));
        cfg.blockDim = dim3(256);
        cfg.stream   = 0;
        cfg.attrs    = pdl_attr;
        cfg.numAttrs = 1;
        cudaLaunchKernelEx(&cfg, sim_kernel, ei, feat, n_edge);
    }
    // Kernel 3: 4 edges per thread (PDL secondary of sim)
    {
        int seg = (n_edge + 3) / 4;
        cudaLaunchConfig_t cfg = {};
        cfg.gridDim  = dim3((unsigned)((seg + 255) / 256));
        cfg.blockDim = dim3(256);
        cfg.stream   = 0;
        cfg.attrs    = pdl_attr;
        cfg.numAttrs = 1;
        cudaLaunchKernelEx(&cfg, finish_kernel, ei, ew, gate, (float*)d_out,
                           n_edge, seg);
    }
}